// round 1
// baseline (speedup 1.0000x reference)
#include <cuda_runtime.h>

// QConv1d: out[n,o,l] = SCALE * sum_{c,k} x[n,c,l+k-4] * w[o,c,k] + bias[o]
// x: (8, 64, 16384) f32   w: (64, 64, 9) f32   bias: (64,) f32
// out: (8, 64, 16384) f32
//
// Block tile: 32 output channels x 128 L positions, one n.
// 256 threads = 8 warps. lane = o_local (0..31), warp = l-group (0..7, 16 L each).
// x reads are warp-broadcast (conflict-free); w reads stride 9 (conflict-free).

#define N_BATCH   8
#define C_IN      64
#define L_IN      16384
#define O_OUT     64
#define KSZ       9
#define PADK      4
#define SCALE     0.125f

#define TILE_L    128
#define TILE_O    32
#define THREADS   256

#define XS_STRIDE (TILE_L + KSZ - 1)      // 136 floats per c row
#define XS_FLOATS (C_IN * XS_STRIDE)      // 8704
#define WS_FLOATS (C_IN * TILE_O * KSZ)   // 18432
#define SMEM_BYTES ((XS_FLOATS + WS_FLOATS) * 4)

__global__ __launch_bounds__(THREADS, 2)
void qconv1d_kernel(const float* __restrict__ x,
                    const float* __restrict__ w,
                    const float* __restrict__ bias,
                    float* __restrict__ out)
{
    extern __shared__ float sm[];
    float* xs = sm;                 // [C_IN][XS_STRIDE]
    float* ws = sm + XS_FLOATS;     // [C_IN][TILE_O][KSZ]  (ws[c*288 + o*9 + k])

    const int tid   = threadIdx.x;
    const int warp  = tid >> 5;     // l-group 0..7
    const int lane  = tid & 31;     // o_local 0..31

    const int tileL = blockIdx.x * TILE_L;
    const int n     = blockIdx.y;
    const int oBase = blockIdx.z * TILE_O;

    const long nOffX = (long)n * C_IN * L_IN;

    // ---- load x tile: c rows [0,64), l in [tileL-4, tileL+132) ----
    {
        const int cBase = warp * 8;
        #pragma unroll
        for (int r = 0; r < 8; ++r) {
            const int c = cBase + r;
            const float* xrow = x + nOffX + (long)c * L_IN;
            float* dst = xs + c * XS_STRIDE;
            #pragma unroll
            for (int j0 = 0; j0 < XS_STRIDE; j0 += 32) {
                int j = j0 + lane;
                if (j < XS_STRIDE) {
                    int gl = tileL - PADK + j;
                    dst[j] = (gl >= 0 && gl < L_IN) ? xrow[gl] : 0.0f;
                }
            }
        }
    }

    // ---- load weight tile: ws[c*288 + o*9 + k] = w[(oBase+o)*576 + c*9 + k] ----
    for (int idx = tid; idx < TILE_O * C_IN * KSZ; idx += THREADS) {
        int o = idx / (C_IN * KSZ);
        int r = idx - o * (C_IN * KSZ);     // = c*9 + k
        int c = r / KSZ;
        int k = r - c * KSZ;
        ws[c * (TILE_O * KSZ) + o * KSZ + k] = w[(long)(oBase + o) * (C_IN * KSZ) + r];
    }

    __syncthreads();

    // ---- compute: each thread -> fixed o=oBase+lane, 16 L at warp*16 ----
    float acc[16];
    #pragma unroll
    for (int i = 0; i < 16; ++i) acc[i] = 0.0f;

    const int xl0 = warp * 16;           // window start in xs row
    const int wo  = lane * KSZ;

    for (int c = 0; c < C_IN; ++c) {
        const float* xr = xs + c * XS_STRIDE + xl0;
        const float* wr = ws + c * (TILE_O * KSZ) + wo;

        float xv[24];
        #pragma unroll
        for (int j = 0; j < 24; ++j) xv[j] = xr[j];   // warp-broadcast LDS

        float wv[KSZ];
        #pragma unroll
        for (int k = 0; k < KSZ; ++k) wv[k] = wr[k];  // conflict-free LDS

        #pragma unroll
        for (int i = 0; i < 16; ++i) {
            #pragma unroll
            for (int k = 0; k < KSZ; ++k)
                acc[i] = fmaf(xv[i + k], wv[k], acc[i]);
        }
    }

    // ---- epilogue: stage to smem, then coalesced float4 stores ----
    const float b = bias[oBase + lane];

    __syncthreads();                 // xs reads done; reuse sm[0..4096) as res
    float* res = sm;                 // [TILE_O][TILE_L]
    #pragma unroll
    for (int i = 0; i < 16; ++i)
        res[lane * TILE_L + xl0 + i] = acc[i] * SCALE + b;
    __syncthreads();

    float* outBase = out + (long)n * O_OUT * L_IN + (long)oBase * L_IN + tileL;
    const float4* res4 = (const float4*)res;
    #pragma unroll
    for (int i = 0; i < 4; ++i) {
        int f   = i * THREADS + tid;        // 0..1023 float4 index
        int flo = f * 4;                    // flat float index
        int o   = flo >> 7;                 // /128
        int l   = flo & 127;
        *(float4*)(outBase + (long)o * L_IN + l) = res4[f];
    }
}

extern "C" void kernel_launch(void* const* d_in, const int* in_sizes, int n_in,
                              void* d_out, int out_size)
{
    const float* x    = (const float*)d_in[0];
    const float* w    = (const float*)d_in[1];
    const float* bias = (const float*)d_in[2];
    float* out        = (float*)d_out;

    cudaFuncSetAttribute(qconv1d_kernel,
                         cudaFuncAttributeMaxDynamicSharedMemorySize, SMEM_BYTES);

    dim3 grid(L_IN / TILE_L, N_BATCH, O_OUT / TILE_O);   // (128, 8, 2)
    qconv1d_kernel<<<grid, THREADS, SMEM_BYTES>>>(x, w, bias, out);
}

// round 3
// speedup vs baseline: 3.2088x; 3.2088x over previous
#include <cuda_runtime.h>
#include <cstdint>

// QConv1d via mma.sync tf32 implicit GEMM (legacy HMMA path; tcgen05 is not
// available because the harness PTX target is compute_103 without the 'a').
//
// out[n,o,l] = 0.125 * sum_{c,k} x[n,c,l+k-4] * w[o,c,k] + bias[o]
// GEMM: M = 128 l-positions per tile, N = 64 (o), K = 576 (kidx = c*9+k).
//
// 256 threads = 8 warps, warp grid 4(M) x 2(N): each warp owns 32x32 of C.
// B (weights) pre-packed once into SMEM in mma-fragment order (conflict-free
// ld.shared.v2). A read directly from the raw x tile in SMEM (implicit im2col).
// All inputs pre-rounded to tf32 so the hot loop has no cvt.

#define N_BATCH 8
#define C_IN    64
#define L_IN    16384
#define O_OUT   64
#define KSZ     9
#define PADK    4
#define SCALEF  0.125f

#define THREADS 256
#define TILE_L  128
#define NTILES  (N_BATCH * (L_IN / TILE_L))   // 1024
#define GRID    148

#define KTOT    (C_IN * KSZ)                  // 576
#define KSTEPS  (KTOT / 8)                    // 72

#define XS_STRIDE 136
#define XS_FLOATS (C_IN * XS_STRIDE)          // 8704

// SMEM layout (bytes)
#define PK_BYTES   (KSTEPS * 256 * 8)         // 147456: [ks][nB][nt][lane] float2
#define SM_PK      0
#define SM_XS      PK_BYTES
#define SM_BIAS    (SM_XS + XS_FLOATS * 4)    // 182272
#define SM_TOTAL   (SM_BIAS + O_OUT * 4)      // 182528

__device__ __forceinline__ uint32_t smem_u32(const void* p) {
    uint32_t a;
    asm("{ .reg .u64 t; cvta.to.shared.u64 t, %1; cvt.u32.u64 %0, t; }" : "=r"(a) : "l"(p));
    return a;
}

__device__ __forceinline__ uint32_t f2tf32(float f) {
    uint32_t r;
    asm("cvt.rna.tf32.f32 %0, %1;" : "=r"(r) : "f"(f));
    return r;
}

__device__ __forceinline__ uint32_t lds_b32(uint32_t a) {
    uint32_t v;
    asm volatile("ld.shared.b32 %0, [%1];" : "=r"(v) : "r"(a));
    return v;
}

__device__ __forceinline__ void lds_v2(uint32_t a, uint32_t& v0, uint32_t& v1) {
    asm volatile("ld.shared.v2.b32 {%0, %1}, [%2];" : "=r"(v0), "=r"(v1) : "r"(a));
}

__device__ __forceinline__ void mma_tf32(float* c, const uint32_t* a, uint32_t b0, uint32_t b1) {
    asm volatile(
        "mma.sync.aligned.m16n8k8.row.col.f32.tf32.tf32.f32 "
        "{%0,%1,%2,%3}, {%4,%5,%6,%7}, {%8,%9}, {%0,%1,%2,%3};"
        : "+f"(c[0]), "+f"(c[1]), "+f"(c[2]), "+f"(c[3])
        : "r"(a[0]), "r"(a[1]), "r"(a[2]), "r"(a[3]), "r"(b0), "r"(b1));
}

__global__ void __launch_bounds__(THREADS, 1)
qconv1d_mma(const float* __restrict__ x, const float* __restrict__ w,
            const float* __restrict__ bias, float* __restrict__ out)
{
    extern __shared__ char smem[];
    float* xs      = (float*)(smem + SM_XS);
    float* bias_sm = (float*)(smem + SM_BIAS);

    const int tid  = threadIdx.x;
    const int wid  = tid >> 5;
    const int lane = tid & 31;
    const int mBlk = wid & 3;        // M block: rows [mBlk*32, +32)
    const int nBlk = wid >> 2;       // N block: cols [nBlk*32, +32)
    const int g    = lane >> 2;      // group id 0..7
    const int tig  = lane & 3;       // thread in group

    // ---- pack weights into fragment order (once per persistent CTA) ----
    // pk float2 index: ks*256 + nB*128 + nt*32 + lane
    // value: {w[o*576 + k0], w[o*576 + k0 + 4]}, o = nB*32+nt*8+(lane>>2), k0 = ks*8+(lane&3)
    {
        uint2* pk = (uint2*)(smem + SM_PK);
        for (int i = tid; i < KSTEPS * 256; i += THREADS) {
            int li = i & 31;
            int nt = (i >> 5) & 3;
            int nB = (i >> 7) & 1;
            int ks = i >> 8;
            int o  = nB * 32 + nt * 8 + (li >> 2);
            int k0 = ks * 8 + (li & 3);
            uint2 v;
            v.x = f2tf32(w[o * KTOT + k0]);
            v.y = f2tf32(w[o * KTOT + k0 + 4]);
            pk[i] = v;
        }
        if (tid < O_OUT) bias_sm[tid] = bias[tid];
    }

    // ---- per-thread A offsets for the 9-step unroll (byte offsets) ----
    // A[m][kidx] = xs[c*136 + m + kk], c = kidx/9, kk = kidx%9.
    int off0[9], off4[9];
    #pragma unroll
    for (int u = 0; u < 9; ++u) {
        int ku = u * 8 + tig;
        off0[u] = ((ku / KSZ) * XS_STRIDE + ku % KSZ) * 4;
        int k4 = ku + 4;
        off4[u] = ((k4 / KSZ) * XS_STRIDE + k4 % KSZ) * 4;
    }

    const uint32_t sbase  = smem_u32(smem);
    const uint32_t xsA    = sbase + SM_XS + (uint32_t)(mBlk * 32 + g) * 4;  // + mt*64 + off
    const uint32_t pkB    = sbase + SM_PK + (uint32_t)(nBlk * 128 + lane) * 8;

    for (int t = blockIdx.x; t < NTILES; t += GRID) {
        const int n     = t >> 7;
        const int tileL = (t & 127) << 7;
        const float* xn = x + (size_t)n * C_IN * L_IN;

        // ---- fill x tile [64 c][136 l], tf32-rounded, zero-padded ----
        for (int i = tid; i < XS_FLOATS; i += THREADS) {
            int c = i / XS_STRIDE;
            int j = i - c * XS_STRIDE;
            int gl = tileL - PADK + j;
            float v = (gl >= 0 && gl < L_IN) ? xn[(size_t)c * L_IN + gl] : 0.0f;
            xs[i] = __uint_as_float(f2tf32(v));
        }
        __syncthreads();

        float acc[2][4][4];
        #pragma unroll
        for (int mt = 0; mt < 2; ++mt)
            #pragma unroll
            for (int nt = 0; nt < 4; ++nt)
                #pragma unroll
                for (int r = 0; r < 4; ++r) acc[mt][nt][r] = 0.0f;

        #pragma unroll 1
        for (int cg = 0; cg < 8; ++cg) {       // channel groups of 8 (72 kidx each)
            const uint32_t pA = xsA + (uint32_t)cg * (8 * XS_STRIDE * 4);
            const uint32_t pB = pkB + (uint32_t)cg * (9 * 2048);
            #pragma unroll
            for (int u = 0; u < 9; ++u) {
                uint32_t a[2][4];
                #pragma unroll
                for (int mt = 0; mt < 2; ++mt) {
                    const uint32_t p = pA + mt * 64;
                    a[mt][0] = lds_b32(p + off0[u]);
                    a[mt][1] = lds_b32(p + off0[u] + 32);
                    a[mt][2] = lds_b32(p + off4[u]);
                    a[mt][3] = lds_b32(p + off4[u] + 32);
                }
                #pragma unroll
                for (int nt = 0; nt < 4; ++nt) {
                    uint32_t b0, b1;
                    lds_v2(pB + u * 2048 + nt * 256, b0, b1);
                    mma_tf32(acc[0][nt], a[0], b0, b1);
                    mma_tf32(acc[1][nt], a[1], b0, b1);
                }
            }
        }
        __syncthreads();   // all warps done reading xs before next tile refill

        // ---- epilogue: scale + bias, direct stores ----
        float* ob = out + (size_t)n * O_OUT * L_IN + tileL;
        #pragma unroll
        for (int mt = 0; mt < 2; ++mt) {
            const int r0 = mBlk * 32 + mt * 16 + g;
            #pragma unroll
            for (int nt = 0; nt < 4; ++nt) {
                const int o0 = nBlk * 32 + nt * 8 + tig * 2;
                const float b0 = bias_sm[o0], b1 = bias_sm[o0 + 1];
                ob[(size_t)o0 * L_IN + r0]           = acc[mt][nt][0] * SCALEF + b0;
                ob[(size_t)(o0 + 1) * L_IN + r0]     = acc[mt][nt][1] * SCALEF + b1;
                ob[(size_t)o0 * L_IN + r0 + 8]       = acc[mt][nt][2] * SCALEF + b0;
                ob[(size_t)(o0 + 1) * L_IN + r0 + 8] = acc[mt][nt][3] * SCALEF + b1;
            }
        }
    }
}

extern "C" void kernel_launch(void* const* d_in, const int* in_sizes, int n_in,
                              void* d_out, int out_size)
{
    const float* x    = (const float*)d_in[0];
    const float* w    = (const float*)d_in[1];
    const float* bias = (const float*)d_in[2];
    float* out        = (float*)d_out;

    cudaFuncSetAttribute(qconv1d_mma,
                         cudaFuncAttributeMaxDynamicSharedMemorySize, SM_TOTAL);
    qconv1d_mma<<<GRID, THREADS, SM_TOTAL>>>(x, w, bias, out);
}

// round 4
// speedup vs baseline: 3.2941x; 1.0266x over previous
#include <cuda_runtime.h>
#include <cstdint>

// QConv1d via mma.sync tf32 implicit GEMM.
// out[n,o,l] = 0.125 * sum_{c,k} x[n,c,l+k-4] * w[o,c,k] + bias[o]
// GEMM: M = 256 l-positions per tile, N = 64 (o), K = 576 (kidx = c*9+k).
//
// 512 threads = 16 warps, warp grid 8(M) x 2(N): each warp owns 32x32 of C.
// B (weights) pre-packed once into SMEM in mma-fragment order; A read directly
// from the raw x tile in SMEM (implicit im2col). Inputs pre-rounded to tf32.

#define N_BATCH 8
#define C_IN    64
#define L_IN    16384
#define O_OUT   64
#define KSZ     9
#define PADK    4
#define SCALEF  0.125f

#define THREADS 512
#define TILE_L  256
#define TPERN   (L_IN / TILE_L)               // 64 tiles per batch row
#define NTILES  (N_BATCH * TPERN)             // 512
#define GRID    148

#define KTOT    (C_IN * KSZ)                  // 576
#define KSTEPS  (KTOT / 8)                    // 72

#define XS_STRIDE (TILE_L + 8)                // 264
#define XS_FLOATS (C_IN * XS_STRIDE)          // 16896

// SMEM layout (bytes)
#define PK_BYTES   (KSTEPS * 256 * 8)         // 147456: [ks][nB][nt][lane] float2
#define SM_PK      0
#define SM_XS      PK_BYTES
#define SM_BIAS    (SM_XS + XS_FLOATS * 4)    // 215040
#define SM_TOTAL   (SM_BIAS + O_OUT * 4)      // 215296

__device__ __forceinline__ uint32_t smem_u32(const void* p) {
    uint32_t a;
    asm("{ .reg .u64 t; cvta.to.shared.u64 t, %1; cvt.u32.u64 %0, t; }" : "=r"(a) : "l"(p));
    return a;
}

__device__ __forceinline__ uint32_t f2tf32(float f) {
    uint32_t r;
    asm("cvt.rna.tf32.f32 %0, %1;" : "=r"(r) : "f"(f));
    return r;
}

__device__ __forceinline__ uint32_t lds_b32(uint32_t a) {
    uint32_t v;
    asm volatile("ld.shared.b32 %0, [%1];" : "=r"(v) : "r"(a));
    return v;
}

__device__ __forceinline__ void lds_v2(uint32_t a, uint32_t& v0, uint32_t& v1) {
    asm volatile("ld.shared.v2.b32 {%0, %1}, [%2];" : "=r"(v0), "=r"(v1) : "r"(a));
}

__device__ __forceinline__ void mma_tf32(float* c, const uint32_t* a, uint32_t b0, uint32_t b1) {
    asm volatile(
        "mma.sync.aligned.m16n8k8.row.col.f32.tf32.tf32.f32 "
        "{%0,%1,%2,%3}, {%4,%5,%6,%7}, {%8,%9}, {%0,%1,%2,%3};"
        : "+f"(c[0]), "+f"(c[1]), "+f"(c[2]), "+f"(c[3])
        : "r"(a[0]), "r"(a[1]), "r"(a[2]), "r"(a[3]), "r"(b0), "r"(b1));
}

__global__ void __launch_bounds__(THREADS, 1)
qconv1d_mma(const float* __restrict__ x, const float* __restrict__ w,
            const float* __restrict__ bias, float* __restrict__ out)
{
    extern __shared__ char smem[];
    float* xs      = (float*)(smem + SM_XS);
    float* bias_sm = (float*)(smem + SM_BIAS);

    const int tid  = threadIdx.x;
    const int wid  = tid >> 5;
    const int lane = tid & 31;
    const int mBlk = wid & 7;        // M block: rows [mBlk*32, +32) of 256
    const int nBlk = wid >> 3;       // N block: cols [nBlk*32, +32) of 64
    const int g    = lane >> 2;      // group id 0..7
    const int tig  = lane & 3;       // thread in group

    // ---- pack weights into fragment order (once per persistent CTA) ----
    // pk float2 index: ks*256 + nB*128 + nt*32 + lane
    // value: {w[o*576 + k0], w[o*576 + k0 + 4]}, o = nB*32+nt*8+(lane>>2), k0 = ks*8+(lane&3)
    {
        uint2* pk = (uint2*)(smem + SM_PK);
        for (int i = tid; i < KSTEPS * 256; i += THREADS) {
            int li = i & 31;
            int nt = (i >> 5) & 3;
            int nB = (i >> 7) & 1;
            int ks = i >> 8;
            int o  = nB * 32 + nt * 8 + (li >> 2);
            int k0 = ks * 8 + (li & 3);
            uint2 v;
            v.x = f2tf32(w[o * KTOT + k0]);
            v.y = f2tf32(w[o * KTOT + k0 + 4]);
            pk[i] = v;
        }
        if (tid < O_OUT) bias_sm[tid] = bias[tid];
    }

    // ---- per-thread A byte offsets for the 9-step unroll ----
    // A[m][kidx] = xs[c*264 + m + kk], c = kidx/9, kk = kidx%9.
    int off0[9], off4[9];
    #pragma unroll
    for (int u = 0; u < 9; ++u) {
        int ku = u * 8 + tig;
        off0[u] = ((ku / KSZ) * XS_STRIDE + ku % KSZ) * 4;
        int k4 = ku + 4;
        off4[u] = ((k4 / KSZ) * XS_STRIDE + k4 % KSZ) * 4;
    }

    const uint32_t sbase = smem_u32(smem);
    const uint32_t xsA   = sbase + SM_XS + (uint32_t)(mBlk * 32 + g) * 4;  // + mt*64B + off
    const uint32_t pkB   = sbase + SM_PK + (uint32_t)(nBlk * 128 + lane) * 8;

    for (int t = blockIdx.x; t < NTILES; t += GRID) {
        const int n     = t / TPERN;
        const int tileL = (t % TPERN) * TILE_L;
        const float* xn = x + (size_t)n * C_IN * L_IN;

        // ---- fill x tile [64 c][264 l] (l = tileL-4 .. tileL+259), tf32, zero-padded ----
        for (int i = tid; i < XS_FLOATS; i += THREADS) {
            int c = i / XS_STRIDE;
            int j = i - c * XS_STRIDE;
            int gl = tileL - PADK + j;
            float v = (gl >= 0 && gl < L_IN) ? xn[(size_t)c * L_IN + gl] : 0.0f;
            xs[i] = __uint_as_float(f2tf32(v));
        }
        __syncthreads();

        float acc[2][4][4];
        #pragma unroll
        for (int mt = 0; mt < 2; ++mt)
            #pragma unroll
            for (int nt = 0; nt < 4; ++nt)
                #pragma unroll
                for (int r = 0; r < 4; ++r) acc[mt][nt][r] = 0.0f;

        #pragma unroll 1
        for (int cg = 0; cg < 8; ++cg) {       // channel groups of 8 (72 kidx each)
            const uint32_t pA = xsA + (uint32_t)cg * (8 * XS_STRIDE * 4);
            const uint32_t pB = pkB + (uint32_t)cg * (9 * 2048);
            #pragma unroll
            for (int u = 0; u < 9; ++u) {
                uint32_t a[2][4];
                #pragma unroll
                for (int mt = 0; mt < 2; ++mt) {
                    const uint32_t p = pA + mt * 64;
                    a[mt][0] = lds_b32(p + off0[u]);
                    a[mt][1] = lds_b32(p + off0[u] + 32);
                    a[mt][2] = lds_b32(p + off4[u]);
                    a[mt][3] = lds_b32(p + off4[u] + 32);
                }
                #pragma unroll
                for (int nt = 0; nt < 4; ++nt) {
                    uint32_t b0, b1;
                    lds_v2(pB + u * 2048 + nt * 256, b0, b1);
                    mma_tf32(acc[0][nt], a[0], b0, b1);
                    mma_tf32(acc[1][nt], a[1], b0, b1);
                }
            }
        }
        __syncthreads();   // all warps done reading xs before next tile refill

        // ---- epilogue: scale + bias, direct stores ----
        float* ob = out + (size_t)n * O_OUT * L_IN + tileL;
        #pragma unroll
        for (int mt = 0; mt < 2; ++mt) {
            const int r0 = mBlk * 32 + mt * 16 + g;
            #pragma unroll
            for (int nt = 0; nt < 4; ++nt) {
                const int o0 = nBlk * 32 + nt * 8 + tig * 2;
                const float b0 = bias_sm[o0], b1 = bias_sm[o0 + 1];
                ob[(size_t)o0 * L_IN + r0]           = acc[mt][nt][0] * SCALEF + b0;
                ob[(size_t)(o0 + 1) * L_IN + r0]     = acc[mt][nt][1] * SCALEF + b1;
                ob[(size_t)o0 * L_IN + r0 + 8]       = acc[mt][nt][2] * SCALEF + b0;
                ob[(size_t)(o0 + 1) * L_IN + r0 + 8] = acc[mt][nt][3] * SCALEF + b1;
            }
        }
    }
}

extern "C" void kernel_launch(void* const* d_in, const int* in_sizes, int n_in,
                              void* d_out, int out_size)
{
    const float* x    = (const float*)d_in[0];
    const float* w    = (const float*)d_in[1];
    const float* bias = (const float*)d_in[2];
    float* out        = (float*)d_out;

    cudaFuncSetAttribute(qconv1d_mma,
                         cudaFuncAttributeMaxDynamicSharedMemorySize, SM_TOTAL);
    qconv1d_mma<<<GRID, THREADS, SM_TOTAL>>>(x, w, bias, out);
}